// round 13
// baseline (speedup 1.0000x reference)
#include <cuda_runtime.h>
#include <cuda_fp16.h>

#define Bn 16
#define Cn 1024
#define Tn 2048
#define Dn 512
#define Sn (Tn / 2)
#define EPSf 1e-5f

typedef unsigned int u32;

// ---------------- scratch (static device arrays) ----------------
__device__ __align__(16) __half g_xt [(size_t)Bn * Tn * Cn];        // x^T (B,T,C)
__device__ __align__(16) __half g_wq [Dn * Cn];
__device__ __align__(16) __half g_wkv[2 * Dn * Cn];                 // [Wk; Wv] stacked
__device__ __align__(16) __half g_wo [Cn * Dn];
__device__ __align__(16) __half g_qt [(size_t)Bn * Tn * Dn];        // Q^T (B,T,D)
__device__ __align__(16) __half g_kv [(size_t)Bn * 2 * Dn * Sn];    // [Kp; Vp] pooled (B,2D,S)
__device__ __align__(16) __half g_mt [(size_t)Bn * Dn * Dn];        // Mt = Kp Vp^T
__device__ __align__(16) __half g_p  [(size_t)Bn * Cn * Dn];        // P = Wo M
__device__ __align__(16) __half g_y  [(size_t)Bn * Cn * Tn];        // pre-BN y (fp16)
__device__ float g_bkv[2 * Dn];
__device__ float g_mean[Cn];
__device__ float g_istd[Cn];

// ---------------- PTX helpers ----------------
__device__ __forceinline__ u32 smem_u32(const void* p) {
    u32 a;
    asm("{ .reg .u64 t; cvta.to.shared.u64 t, %1; cvt.u32.u64 %0, t; }" : "=r"(a) : "l"(p));
    return a;
}

#define CPA16(dst, src) \
    asm volatile("cp.async.cg.shared.global [%0], [%1], 16;" :: "r"(dst), "l"(src) : "memory")
#define CP_COMMIT() asm volatile("cp.async.commit_group;" ::: "memory")

#define LDSM4(r, a) \
    asm volatile("ldmatrix.sync.aligned.m8n8.x4.shared.b16 {%0,%1,%2,%3}, [%4];" \
        : "=r"((r)[0]), "=r"((r)[1]), "=r"((r)[2]), "=r"((r)[3]) : "r"(a))

// fp16-accumulate MMA (rt8 class per ncu peak-sustained baseline; the f32-acc
// variant measured rt~16 across 5 structurally different mainloops).
// D,C are 2x b32 = 4 halves: c0={d0,d1} (col c,c+1), c1={d2,d3} (row+8).
#define MMA_H_INIT(c, a, b0, b1, zr) \
    asm volatile("mma.sync.aligned.m16n8k16.row.col.f16.f16.f16.f16 " \
        "{%0,%1}, {%2,%3,%4,%5}, {%6,%7}, {%8,%9};" \
        : "=r"((c)[0]), "=r"((c)[1]) \
        : "r"((a)[0]), "r"((a)[1]), "r"((a)[2]), "r"((a)[3]), \
          "r"(b0), "r"(b1), "r"(zr), "r"(zr))

#define MMA_H_ACC(c, a, b0, b1) \
    asm volatile("mma.sync.aligned.m16n8k16.row.col.f16.f16.f16.f16 " \
        "{%0,%1}, {%2,%3,%4,%5}, {%6,%7}, {%0,%1};" \
        : "+r"((c)[0]), "+r"((c)[1]) \
        : "r"((a)[0]), "r"((a)[1]), "r"((a)[2]), "r"((a)[3]), "r"(b0), "r"(b1))

__device__ __forceinline__ u32 pack_h2(float v0, float v1) {
    __half h0 = __float2half_rn(v0), h1 = __float2half_rn(v1);
    return (u32)__half_as_ushort(h0) | ((u32)__half_as_ushort(h1) << 16);
}

// ---------------- warp-MMA fp16-acc GEMM ----------------
// C(M,N) = alpha * A(M,K) * Bt(N,K)^T + bias
// A, Bt row-major K-major fp16. Requires K % 128 == 0.
// Inner product: fp16-accumulate chains over each BK=64 iter (4 MMAs),
// promoted into persistent fp32 accumulators once per iter (error model:
// ~2e-4 abs per k64 chain set; final rel_err ~2e-4 after BN damping).
// BIAS: 0 none, 1 per-row, 2 per-col.
// OMODE: 1 fp16; 3 pool2 along N -> fp16 (N halves).
// CTA 128x128, 8 warps of 32x64, 256 thr, 2 CTA/SM; BK=64, 3-stage ring
// (prologue commits 2 groups; wait_group 1 at iter kt guarantees tile kt).
// 144B-padded rows (conflict-free ldmatrix).
#define TILE_B 18432           // 128 rows * 144 B
#define BUF_B  (2 * TILE_B)    // A, B
#define SMEM_B (3 * BUF_B)     // 3-stage = 110592 (2 CTAs = 216 KB)

template <int BIAS, int OMODE>
__global__ void __launch_bounds__(256, 2) wgemm(
    const __half* __restrict__ A, const __half* __restrict__ Bt,
    const float* __restrict__ bias,
    __half* __restrict__ Ch,
    int M, int N, int K, float alpha,
    size_t sA, size_t sB, size_t sC)
{
    extern __shared__ __align__(128) char smem[];
    const u32 sbase = smem_u32(smem);
    const int tid = threadIdx.x;
    const int lane = tid & 31;
    const int warp = tid >> 5;
    const int wr = warp >> 1;       // 0..3 -> 32-row block
    const int wc = warp & 1;        // 0..1 -> 64-col block

    A  += (size_t)blockIdx.z * sA;
    Bt += (size_t)blockIdx.z * sB;
    const size_t coff = (size_t)blockIdx.z * sC;

    const int brow = blockIdx.y * 128;
    const int bcol = blockIdx.x * 128;
    const int KT = K >> 6;          // number of BK=64 steps

    // ---- streaming load pointers (computed once) ----
    const int rA = tid >> 3;              // 0..31
    const int cA = (tid & 7) * 8;         // 0..56 halfs (16B chunks)
    const __half* pA = A  + (size_t)(brow + rA) * K + cA;
    const __half* pB = Bt + (size_t)(bcol + rA) * K + cA;
    const size_t rskip = (size_t)32 * K;  // next 32-row group
    const u32 dA = sbase + (u32)(rA * 144 + (tid & 7) * 16);
    const u32 dB = dA + TILE_B;

    auto load_at = [&](u32 bufoff, const __half* a, const __half* b) {
#pragma unroll
        for (int it = 0; it < 4; it++) {
            CPA16(dA + bufoff + (u32)it * (32 * 144), a + (size_t)it * rskip);
            CPA16(dB + bufoff + (u32)it * (32 * 144), b + (size_t)it * rskip);
        }
    };

    float acc[2][8][4];
#pragma unroll
    for (int i = 0; i < 2; i++)
#pragma unroll
        for (int j = 0; j < 8; j++)
#pragma unroll
            for (int q = 0; q < 4; q++) acc[i][j][q] = 0.f;

    // ---- 3-stage prologue: load k-tiles 0,1 (2 committed groups) ----
    load_at(0,     pA,      pB);      CP_COMMIT();
    load_at(BUF_B, pA + 64, pB + 64); CP_COMMIT();
    const __half* qA = pA + 128;
    const __half* qB = pB + 128;

    const u32 rowoff = (u32)(((lane >> 3) & 1) * 8 + (lane & 7));
    const u32 chsel  = (u32)(lane >> 4);
    const u32 aoff = (u32)(wr * 32 + rowoff) * 144 + chsel * 16;
    const u32 boff = TILE_B + (u32)(wc * 64 + rowoff) * 144 + chsel * 16;

    const u32 zr = 0;

    int buf = 0;
    for (int kt = 0; kt < KT; kt++) {
        asm volatile("cp.async.wait_group 1;" ::: "memory");
        __syncthreads();   // tile kt visible; next write buffer reusable

        if (kt + 2 < KT) {
            int nb = buf + 2; if (nb >= 3) nb -= 3;
            load_at((u32)nb * BUF_B, qA, qB);
            qA += 64; qB += 64;
        }
        CP_COMMIT();       // one group per iter (possibly empty at tail)

        const u32 at = sbase + (u32)buf * BUF_B;
        const u32 abase = at + aoff;
        const u32 bbase = at + boff;

        // ---- fp16-acc chains over the 4 k16 substeps of this BK=64 ----
        u32 ch[2][8][2];
#pragma unroll
        for (int ks = 0; ks < 4; ks++) {
            const u32 choff = (u32)ks * 32;
            u32 ar[2][4];
#pragma unroll
            for (int i = 0; i < 2; i++)
                LDSM4(ar[i], abase + (u32)i * (16 * 144) + choff);
            u32 br[4][4];
#pragma unroll
            for (int j4 = 0; j4 < 4; j4++)
                LDSM4(br[j4], bbase + (u32)j4 * (16 * 144) + choff);
#pragma unroll
            for (int i = 0; i < 2; i++)
#pragma unroll
                for (int j = 0; j < 8; j++) {
                    const int j4 = j >> 1, h = j & 1;
                    if (ks == 0) MMA_H_INIT(ch[i][j], ar[i], br[j4][h], br[j4][h + 2], zr);
                    else         MMA_H_ACC (ch[i][j], ar[i], br[j4][h], br[j4][h + 2]);
                }
        }
        // ---- promote chain results into fp32 accumulators ----
#pragma unroll
        for (int i = 0; i < 2; i++)
#pragma unroll
            for (int j = 0; j < 8; j++) {
                const float2 f0 = __half22float2(*(const __half2*)&ch[i][j][0]);
                const float2 f1 = __half22float2(*(const __half2*)&ch[i][j][1]);
                acc[i][j][0] += f0.x;
                acc[i][j][1] += f0.y;
                acc[i][j][2] += f1.x;
                acc[i][j][3] += f1.y;
            }
        if (++buf == 3) buf = 0;
    }

    // ---------------- epilogue ----------------
    const int r0 = brow + wr * 32 + (lane >> 2);
    const int c0l = wc * 64 + (lane & 3) * 2;
#pragma unroll
    for (int i = 0; i < 2; i++) {
#pragma unroll
        for (int half = 0; half < 2; half++) {
            const int row = r0 + i * 16 + half * 8;
            const float badd = (BIAS == 1) ? bias[row] : 0.f;
#pragma unroll
            for (int j = 0; j < 8; j++) {
                const int col = bcol + c0l + j * 8;
                float v0 = alpha * acc[i][j][half * 2 + 0] + badd;
                float v1 = alpha * acc[i][j][half * 2 + 1] + badd;
                if (BIAS == 2) { v0 += bias[col]; v1 += bias[col + 1]; }
                if (OMODE == 1) {
                    *(u32*)(Ch + coff + (size_t)row * N + col) = pack_h2(v0, v1);
                } else { // OMODE == 3: maxpool pairs of adjacent cols
                    Ch[coff + (size_t)row * (N >> 1) + (col >> 1)] =
                        __float2half_rn(fmaxf(v0, v1));
                }
            }
        }
    }
}

// ---------------- x (B,C,T) fp32 -> x^T (B,T,C) fp16 ----------------
__global__ void xtrans(const float* __restrict__ x, __half* __restrict__ o)
{
    __shared__ float s[32][33];
    const int b = blockIdx.z;
    const int c0 = blockIdx.y * 32;
    const int t0 = blockIdx.x * 32;
    const int tid = threadIdx.x;
    for (int i = tid; i < 1024; i += 256) {
        const int r = i >> 5, cc = i & 31;
        s[r][cc] = x[((size_t)b * Cn + c0 + r) * Tn + t0 + cc];
    }
    __syncthreads();
    for (int i = tid; i < 512; i += 256) {
        const int r = i >> 4, cp = (i & 15) * 2;
        const size_t oo = ((size_t)b * Tn + t0 + r) * Cn + c0 + cp;
        *(u32*)(o + oo) = pack_h2(s[cp][r], s[cp + 1][r]);
    }
}

// ---------------- 4x weight fp32 -> fp16 (one launch) ----------------
__global__ void wconv4(const float* __restrict__ w0, const float* __restrict__ w1,
                       const float* __restrict__ w2, const float* __restrict__ w3,
                       __half* __restrict__ o0, __half* __restrict__ o1,
                       __half* __restrict__ o2, __half* __restrict__ o3, size_t n4)
{
    const size_t i = (size_t)blockIdx.x * blockDim.x + threadIdx.x;
    if (i >= n4) return;
    const float* srcs[4] = {w0, w1, w2, w3};
    __half* dsts[4] = {o0, o1, o2, o3};
    const float4 v = ((const float4*)srcs[blockIdx.y])[i];
    ((uint2*)dsts[blockIdx.y])[i] = make_uint2(pack_h2(v.x, v.y), pack_h2(v.z, v.w));
}

// ---------------- stack bk|bv into one bias vector ----------------
__global__ void packbias(const float* __restrict__ bk, const float* __restrict__ bv,
                         float* __restrict__ o)
{
    const int i = blockIdx.x * blockDim.x + threadIdx.x;
    if (i < Dn) o[i] = bk[i];
    else if (i < 2 * Dn) o[i] = bv[i - Dn];
}

// ---------------- BN batch stats (fp16 y) ----------------
__global__ void bn_stats(const __half* __restrict__ y,
                         float* __restrict__ mean, float* __restrict__ istd)
{
    const int c = blockIdx.x;
    float s = 0.f, s2 = 0.f;
    for (int b = 0; b < Bn; b++) {
        const __half* row = y + ((size_t)b * Cn + c) * Tn;
        for (int t = threadIdx.x * 8; t < Tn; t += blockDim.x * 8) {
            const uint4 u = *(const uint4*)(row + t);
            const u32 w[4] = {u.x, u.y, u.z, u.w};
#pragma unroll
            for (int q = 0; q < 4; q++) {
                const float2 f = __half22float2(*(const __half2*)&w[q]);
                s  += f.x + f.y;
                s2 += f.x * f.x + f.y * f.y;
            }
        }
    }
#pragma unroll
    for (int o = 16; o > 0; o >>= 1) {
        s  += __shfl_down_sync(0xffffffffu, s,  o);
        s2 += __shfl_down_sync(0xffffffffu, s2, o);
    }
    __shared__ float ss[32], ss2[32];
    const int lane = threadIdx.x & 31, w = threadIdx.x >> 5;
    if (lane == 0) { ss[w] = s; ss2[w] = s2; }
    __syncthreads();
    if (w == 0) {
        const int nw = blockDim.x >> 5;
        s  = lane < nw ? ss[lane]  : 0.f;
        s2 = lane < nw ? ss2[lane] : 0.f;
#pragma unroll
        for (int o = 16; o > 0; o >>= 1) {
            s  += __shfl_down_sync(0xffffffffu, s,  o);
            s2 += __shfl_down_sync(0xffffffffu, s2, o);
        }
        if (lane == 0) {
            const float n = (float)(Bn * Tn);
            const float m = s / n;
            mean[c] = m;
            istd[c] = rsqrtf(s2 / n - m * m + EPSf);
        }
    }
}

// ---------------- BN apply + residual ----------------
__global__ void bn_apply(const __half* __restrict__ y, const float* __restrict__ x,
                         const float* __restrict__ mean, const float* __restrict__ istd,
                         const float* __restrict__ gamma, const float* __restrict__ beta,
                         float* __restrict__ out)
{
    const size_t i4 = ((size_t)blockIdx.x * blockDim.x + threadIdx.x) * 4;
    const size_t total = (size_t)Bn * Cn * Tn;
    if (i4 >= total) return;
    const int c = (int)((i4 / Tn) % Cn);
    const float g = gamma[c] * istd[c];
    const float m = mean[c];
    const float bt = beta[c];
    const uint2 u = *(const uint2*)(y + i4);
    const float2 f0 = __half22float2(*(const __half2*)&u.x);
    const float2 f1 = __half22float2(*(const __half2*)&u.y);
    const float4 xv = *(const float4*)(x + i4);
    float4 o;
    o.x = g * (f0.x - m) + bt + xv.x;
    o.y = g * (f0.y - m) + bt + xv.y;
    o.z = g * (f1.x - m) + bt + xv.z;
    o.w = g * (f1.y - m) + bt + xv.w;
    *(float4*)(out + i4) = o;
}

extern "C" void kernel_launch(void* const* d_in, const int* in_sizes, int n_in,
                              void* d_out, int out_size)
{
    const float* x     = (const float*)d_in[0];
    const float* Wq    = (const float*)d_in[1];
    const float* bq    = (const float*)d_in[2];
    const float* Wk    = (const float*)d_in[3];
    const float* bk    = (const float*)d_in[4];
    const float* Wv    = (const float*)d_in[5];
    const float* bv    = (const float*)d_in[6];
    const float* Wo    = (const float*)d_in[7];
    const float* bo    = (const float*)d_in[8];
    const float* gamma = (const float*)d_in[9];
    const float* beta  = (const float*)d_in[10];
    float* out = (float*)d_out;

    __half *xt, *wq, *wkv, *wo, *qt, *kv, *mt, *pp, *yp;
    float *bkv, *mean, *istd;
    cudaGetSymbolAddress((void**)&xt,  g_xt);
    cudaGetSymbolAddress((void**)&wq,  g_wq);
    cudaGetSymbolAddress((void**)&wkv, g_wkv);
    cudaGetSymbolAddress((void**)&wo,  g_wo);
    cudaGetSymbolAddress((void**)&qt,  g_qt);
    cudaGetSymbolAddress((void**)&kv,  g_kv);
    cudaGetSymbolAddress((void**)&mt,  g_mt);
    cudaGetSymbolAddress((void**)&pp,  g_p);
    cudaGetSymbolAddress((void**)&yp,  g_y);
    cudaGetSymbolAddress((void**)&bkv, g_bkv);
    cudaGetSymbolAddress((void**)&mean, g_mean);
    cudaGetSymbolAddress((void**)&istd, g_istd);

    cudaFuncSetAttribute(wgemm<1, 3>, cudaFuncAttributeMaxDynamicSharedMemorySize, SMEM_B);
    cudaFuncSetAttribute(wgemm<2, 1>, cudaFuncAttributeMaxDynamicSharedMemorySize, SMEM_B);
    cudaFuncSetAttribute(wgemm<0, 1>, cudaFuncAttributeMaxDynamicSharedMemorySize, SMEM_B);
    cudaFuncSetAttribute(wgemm<1, 1>, cudaFuncAttributeMaxDynamicSharedMemorySize, SMEM_B);

    // conversions
    xtrans<<<dim3(Tn / 32, Cn / 32, Bn), 256>>>(x, xt);
    const size_t nw4 = (size_t)Dn * Cn / 4;   // per weight tensor
    wconv4<<<dim3((unsigned)((nw4 + 255) / 256), 4), 256>>>(
        Wk, Wv, Wq, Wo, wkv, wkv + (size_t)Dn * Cn, wq, wo, nw4);
    packbias<<<4, 256>>>(bk, bv, bkv);

    const size_t sTC  = (size_t)Tn * Cn;
    const size_t sTD  = (size_t)Tn * Dn;
    const size_t s2DS = (size_t)2 * Dn * Sn;
    const size_t sDD  = (size_t)Dn * Dn;
    const size_t sCD  = (size_t)Cn * Dn;
    const size_t sCT  = (size_t)Cn * Tn;

    // KV proj + fused pool: [Kp;Vp](2D,S) = pool2(Wkv x + bkv)
    const dim3 gkv(Tn / 128, 2 * Dn / 128, Bn);
    wgemm<1, 3><<<gkv, 256, SMEM_B>>>(wkv, xt, bkv, kv, 2 * Dn, Tn, Cn, 1.f, 0, sTC, s2DS);

    // Q^T(T,D) = xT Wq^T + bq(col)
    const dim3 gq(Dn / 128, Tn / 128, Bn);
    wgemm<2, 1><<<gq, 256, SMEM_B>>>(xt, wq, bq, qt, Tn, Dn, Cn, 1.f, sTC, 0, sTD);

    // Mt(D,D) = Kp Vp^T  (= M^T)
    const dim3 gm(Dn / 128, Dn / 128, Bn);
    wgemm<0, 1><<<gm, 256, SMEM_B>>>(kv, kv + (size_t)Dn * Sn, nullptr, mt,
                                     Dn, Dn, Sn, 1.f, s2DS, s2DS, sDD);

    // P(C,D) = Wo M = Wo Mt^T
    const dim3 gp(Dn / 128, Cn / 128, Bn);
    wgemm<0, 1><<<gp, 256, SMEM_B>>>(wo, mt, nullptr, pp, Cn, Dn, Dn, 1.f, 0, sDD, sCD);

    // y(C,T) = (1/T) P Q + bo
    const dim3 gy(Tn / 128, Cn / 128, Bn);
    wgemm<1, 1><<<gy, 256, SMEM_B>>>(pp, qt, bo, yp, Cn, Tn, Dn, 1.f / (float)Tn,
                                     sCD, sTD, sCT);

    // BatchNorm + residual
    bn_stats<<<Cn, 256>>>(yp, mean, istd);
    const size_t total4 = (size_t)Bn * Cn * Tn / 4;
    bn_apply<<<(unsigned)((total4 + 255) / 256), 256>>>(yp, x, mean, istd, gamma, beta, out);
}

// round 14
// speedup vs baseline: 1.1261x; 1.1261x over previous
#include <cuda_runtime.h>
#include <cuda_fp16.h>

#define Bn 16
#define Cn 1024
#define Tn 2048
#define Dn 512
#define Sn (Tn / 2)
#define EPSf 1e-5f

typedef unsigned int u32;

// ---------------- scratch (static device arrays) ----------------
__device__ __align__(16) __half g_xt [(size_t)Bn * Tn * Cn];        // x^T (B,T,C)
__device__ __align__(16) __half g_wq [Dn * Cn];
__device__ __align__(16) __half g_wkv[2 * Dn * Cn];                 // [Wk; Wv] stacked
__device__ __align__(16) __half g_wo [Cn * Dn];
__device__ __align__(16) __half g_qt [(size_t)Bn * Tn * Dn];        // Q^T (B,T,D)
__device__ __align__(16) __half g_kv [(size_t)Bn * 2 * Dn * Sn];    // [Kp; Vp] pooled (B,2D,S)
__device__ __align__(16) __half g_mt [(size_t)Bn * Dn * Dn];        // Mt = Kp Vp^T
__device__ __align__(16) __half g_p  [(size_t)Bn * Cn * Dn];        // P = Wo M
__device__ __align__(16) __half g_y  [(size_t)Bn * Cn * Tn];        // pre-BN y (fp16)
__device__ float g_bkv[2 * Dn];
__device__ float g_sum[Cn];
__device__ float g_sq [Cn];
__device__ float g_mean[Cn];
__device__ float g_istd[Cn];

// ---------------- PTX helpers ----------------
__device__ __forceinline__ u32 smem_u32(const void* p) {
    u32 a;
    asm("{ .reg .u64 t; cvta.to.shared.u64 t, %1; cvt.u32.u64 %0, t; }" : "=r"(a) : "l"(p));
    return a;
}

#define CPA16(dst, src) \
    asm volatile("cp.async.cg.shared.global [%0], [%1], 16;" :: "r"(dst), "l"(src) : "memory")
#define CP_COMMIT() asm volatile("cp.async.commit_group;" ::: "memory")

#define LDSM4(r, a) \
    asm volatile("ldmatrix.sync.aligned.m8n8.x4.shared.b16 {%0,%1,%2,%3}, [%4];" \
        : "=r"((r)[0]), "=r"((r)[1]), "=r"((r)[2]), "=r"((r)[3]) : "r"(a))

#define MMA_F16(d, a, b0, b1) \
    asm volatile("mma.sync.aligned.m16n8k16.row.col.f32.f16.f16.f32 " \
        "{%0,%1,%2,%3}, {%4,%5,%6,%7}, {%8,%9}, {%0,%1,%2,%3};" \
        : "+f"((d)[0]), "+f"((d)[1]), "+f"((d)[2]), "+f"((d)[3]) \
        : "r"((a)[0]), "r"((a)[1]), "r"((a)[2]), "r"((a)[3]), "r"(b0), "r"(b1))

__device__ __forceinline__ u32 pack_h2(float v0, float v1) {
    __half h0 = __float2half_rn(v0), h1 = __float2half_rn(v1);
    return (u32)__half_as_ushort(h0) | ((u32)__half_as_ushort(h1) << 16);
}

// ---------------- warp-MMA plain-fp16 GEMM (R12 mainloop, proven) ----------
// C(M,N) = alpha * A(M,K) * Bt(N,K)^T + bias
// A, Bt row-major K-major fp16; fp32 accumulate. Requires K % 128 == 0.
// BIAS: 0 none, 1 per-row, 2 per-col.
// OMODE: 1 fp16; 3 pool2 along N -> fp16 (N halves);
//        5 fp16 + fused per-row (channel) sum/sumsq atomics for BatchNorm.
// CTA 128x128, 8 warps of 32x64, 256 thr, 2 CTA/SM; BK=64, 3-stage ring
// (prologue commits 2 groups; wait_group 1 at iter kt guarantees tile kt).
// Six mainloop variants (R8-R13) all pinned at ~0.26 MMA/cyc/SM: this is
// the sm_103 mma.sync issue ceiling; mainloop frozen from here.
#define TILE_B 18432           // 128 rows * 144 B
#define BUF_B  (2 * TILE_B)    // A, B
#define SMEM_B (3 * BUF_B)     // 3-stage = 110592 (2 CTAs = 216 KB)

template <int BIAS, int OMODE>
__global__ void __launch_bounds__(256, 2) wgemm(
    const __half* __restrict__ A, const __half* __restrict__ Bt,
    const float* __restrict__ bias,
    __half* __restrict__ Ch,
    float* __restrict__ gsum, float* __restrict__ gsq,
    int M, int N, int K, float alpha,
    size_t sA, size_t sB, size_t sC)
{
    extern __shared__ __align__(128) char smem[];
    const u32 sbase = smem_u32(smem);
    const int tid = threadIdx.x;
    const int lane = tid & 31;
    const int warp = tid >> 5;
    const int wr = warp >> 1;       // 0..3 -> 32-row block
    const int wc = warp & 1;        // 0..1 -> 64-col block

    A  += (size_t)blockIdx.z * sA;
    Bt += (size_t)blockIdx.z * sB;
    const size_t coff = (size_t)blockIdx.z * sC;

    const int brow = blockIdx.y * 128;
    const int bcol = blockIdx.x * 128;
    const int KT = K >> 6;          // number of BK=64 steps

    // ---- streaming load pointers (computed once) ----
    const int rA = tid >> 3;              // 0..31
    const int cA = (tid & 7) * 8;         // 0..56 halfs (16B chunks)
    const __half* pA = A  + (size_t)(brow + rA) * K + cA;
    const __half* pB = Bt + (size_t)(bcol + rA) * K + cA;
    const size_t rskip = (size_t)32 * K;  // next 32-row group
    const u32 dA = sbase + (u32)(rA * 144 + (tid & 7) * 16);
    const u32 dB = dA + TILE_B;

    auto load_at = [&](u32 bufoff, const __half* a, const __half* b) {
#pragma unroll
        for (int it = 0; it < 4; it++) {
            CPA16(dA + bufoff + (u32)it * (32 * 144), a + (size_t)it * rskip);
            CPA16(dB + bufoff + (u32)it * (32 * 144), b + (size_t)it * rskip);
        }
    };

    float acc[2][8][4];
#pragma unroll
    for (int i = 0; i < 2; i++)
#pragma unroll
        for (int j = 0; j < 8; j++)
#pragma unroll
            for (int q = 0; q < 4; q++) acc[i][j][q] = 0.f;

    // ---- 3-stage prologue: load k-tiles 0,1 (2 committed groups) ----
    load_at(0,     pA,      pB);      CP_COMMIT();
    load_at(BUF_B, pA + 64, pB + 64); CP_COMMIT();
    const __half* qA = pA + 128;
    const __half* qB = pB + 128;

    const u32 rowoff = (u32)(((lane >> 3) & 1) * 8 + (lane & 7));
    const u32 chsel  = (u32)(lane >> 4);
    const u32 aoff = (u32)(wr * 32 + rowoff) * 144 + chsel * 16;
    const u32 boff = TILE_B + (u32)(wc * 64 + rowoff) * 144 + chsel * 16;

    int buf = 0;
    for (int kt = 0; kt < KT; kt++) {
        asm volatile("cp.async.wait_group 1;" ::: "memory");
        __syncthreads();   // tile kt visible; next write buffer reusable

        if (kt + 2 < KT) {
            int nb = buf + 2; if (nb >= 3) nb -= 3;
            load_at((u32)nb * BUF_B, qA, qB);
            qA += 64; qB += 64;
        }
        CP_COMMIT();       // one group per iter (possibly empty at tail)

        const u32 at = sbase + (u32)buf * BUF_B;
        const u32 abase = at + aoff;
        const u32 bbase = at + boff;

        // ---- fragment-pipelined 4x k16 substeps ----
        u32 ar[2][4];        // A frags, single buffer
        u32 br[2][4][4];     // B frags, double buffer
#pragma unroll
        for (int j4 = 0; j4 < 4; j4++)
            LDSM4(br[0][j4], bbase + (u32)j4 * (16 * 144));
#pragma unroll
        for (int i = 0; i < 2; i++)
            LDSM4(ar[i], abase + (u32)i * (16 * 144));

#pragma unroll
        for (int ks = 0; ks < 4; ks++) {
            const int cur = ks & 1;
            const int nxt = cur ^ 1;
            const u32 nchoff = (u32)(ks + 1) * 32;
            if (ks < 3) {
#pragma unroll
                for (int j4 = 0; j4 < 4; j4++)
                    LDSM4(br[nxt][j4], bbase + (u32)j4 * (16 * 144) + nchoff);
            }
#pragma unroll
            for (int i = 0; i < 2; i++)
#pragma unroll
                for (int j = 0; j < 8; j++) {
                    const int j4 = j >> 1, h = j & 1;
                    MMA_F16(acc[i][j], ar[i], br[cur][j4][h], br[cur][j4][h + 2]);
                }
            if (ks < 3) {
#pragma unroll
                for (int i = 0; i < 2; i++)
                    LDSM4(ar[i], abase + (u32)i * (16 * 144) + nchoff);
            }
        }
        if (++buf == 3) buf = 0;
    }

    // ---------------- epilogue ----------------
    const int r0 = brow + wr * 32 + (lane >> 2);
    const int c0l = wc * 64 + (lane & 3) * 2;
#pragma unroll
    for (int i = 0; i < 2; i++) {
#pragma unroll
        for (int half = 0; half < 2; half++) {
            const int row = r0 + i * 16 + half * 8;
            const float badd = (BIAS == 1) ? bias[row] : 0.f;
            float st = 0.f, st2 = 0.f;
#pragma unroll
            for (int j = 0; j < 8; j++) {
                const int col = bcol + c0l + j * 8;
                float v0 = alpha * acc[i][j][half * 2 + 0] + badd;
                float v1 = alpha * acc[i][j][half * 2 + 1] + badd;
                if (BIAS == 2) { v0 += bias[col]; v1 += bias[col + 1]; }
                if (OMODE == 1 || OMODE == 5) {
                    *(u32*)(Ch + coff + (size_t)row * N + col) = pack_h2(v0, v1);
                    if (OMODE == 5) {
                        st  += v0 + v1;
                        st2 += v0 * v0 + v1 * v1;
                    }
                } else { // OMODE == 3: maxpool pairs of adjacent cols
                    Ch[coff + (size_t)row * (N >> 1) + (col >> 1)] =
                        __float2half_rn(fmaxf(v0, v1));
                }
            }
            if (OMODE == 5) {
                // quad lanes (lane&3) share this row; reduce then leader-atomics
                st  += __shfl_xor_sync(0xffffffffu, st,  1);
                st  += __shfl_xor_sync(0xffffffffu, st,  2);
                st2 += __shfl_xor_sync(0xffffffffu, st2, 1);
                st2 += __shfl_xor_sync(0xffffffffu, st2, 2);
                if ((lane & 3) == 0) {
                    atomicAdd(gsum + row, st);
                    atomicAdd(gsq  + row, st2);
                }
            }
        }
    }
}

// ---------------- x (B,C,T) fp32 -> x^T (B,T,C) fp16 ----------------
__global__ void xtrans(const float* __restrict__ x, __half* __restrict__ o)
{
    __shared__ float s[32][33];
    const int b = blockIdx.z;
    const int c0 = blockIdx.y * 32;
    const int t0 = blockIdx.x * 32;
    const int tid = threadIdx.x;
    for (int i = tid; i < 1024; i += 256) {
        const int r = i >> 5, cc = i & 31;
        s[r][cc] = x[((size_t)b * Cn + c0 + r) * Tn + t0 + cc];
    }
    __syncthreads();
    for (int i = tid; i < 512; i += 256) {
        const int r = i >> 4, cp = (i & 15) * 2;
        const size_t oo = ((size_t)b * Tn + t0 + r) * Cn + c0 + cp;
        *(u32*)(o + oo) = pack_h2(s[cp][r], s[cp + 1][r]);
    }
}

// ---------------- 4x weight fp32 -> fp16 (one launch) ----------------
__global__ void wconv4(const float* __restrict__ w0, const float* __restrict__ w1,
                       const float* __restrict__ w2, const float* __restrict__ w3,
                       __half* __restrict__ o0, __half* __restrict__ o1,
                       __half* __restrict__ o2, __half* __restrict__ o3, size_t n4)
{
    const size_t i = (size_t)blockIdx.x * blockDim.x + threadIdx.x;
    if (i >= n4) return;
    const float* srcs[4] = {w0, w1, w2, w3};
    __half* dsts[4] = {o0, o1, o2, o3};
    const float4 v = ((const float4*)srcs[blockIdx.y])[i];
    ((uint2*)dsts[blockIdx.y])[i] = make_uint2(pack_h2(v.x, v.y), pack_h2(v.z, v.w));
}

// ---------------- stack bk|bv + zero the BN stat accumulators ----------
__global__ void packbias_zstats(const float* __restrict__ bk, const float* __restrict__ bv,
                                float* __restrict__ o, float* __restrict__ gsum,
                                float* __restrict__ gsq)
{
    const int i = blockIdx.x * blockDim.x + threadIdx.x;
    if (i < Dn) o[i] = bk[i];
    else if (i < 2 * Dn) o[i] = bv[i - Dn];
    if (i < Cn) { gsum[i] = 0.f; gsq[i] = 0.f; }
}

// ---------------- finalize BN stats from fused sums --------------------
__global__ void bnfin(const float* __restrict__ gsum, const float* __restrict__ gsq,
                      float* __restrict__ mean, float* __restrict__ istd)
{
    const int c = blockIdx.x * blockDim.x + threadIdx.x;
    if (c >= Cn) return;
    const float n = (float)(Bn * Tn);
    const float m = gsum[c] / n;
    mean[c] = m;
    istd[c] = rsqrtf(gsq[c] / n - m * m + EPSf);
}

// ---------------- BN apply + residual ------------------------------------
__global__ void bn_apply(const __half* __restrict__ y, const float* __restrict__ x,
                         const float* __restrict__ mean, const float* __restrict__ istd,
                         const float* __restrict__ gamma, const float* __restrict__ beta,
                         float* __restrict__ out)
{
    const size_t i4 = ((size_t)blockIdx.x * blockDim.x + threadIdx.x) * 4;
    const size_t total = (size_t)Bn * Cn * Tn;
    if (i4 >= total) return;
    const int c = (int)((i4 / Tn) % Cn);
    const float g = gamma[c] * istd[c];
    const float m = mean[c];
    const float bt = beta[c];
    const uint2 u = *(const uint2*)(y + i4);
    const float2 f0 = __half22float2(*(const __half2*)&u.x);
    const float2 f1 = __half22float2(*(const __half2*)&u.y);
    const float4 xv = *(const float4*)(x + i4);
    float4 o;
    o.x = g * (f0.x - m) + bt + xv.x;
    o.y = g * (f0.y - m) + bt + xv.y;
    o.z = g * (f1.x - m) + bt + xv.z;
    o.w = g * (f1.y - m) + bt + xv.w;
    *(float4*)(out + i4) = o;
}

extern "C" void kernel_launch(void* const* d_in, const int* in_sizes, int n_in,
                              void* d_out, int out_size)
{
    const float* x     = (const float*)d_in[0];
    const float* Wq    = (const float*)d_in[1];
    const float* bq    = (const float*)d_in[2];
    const float* Wk    = (const float*)d_in[3];
    const float* bk    = (const float*)d_in[4];
    const float* Wv    = (const float*)d_in[5];
    const float* bv    = (const float*)d_in[6];
    const float* Wo    = (const float*)d_in[7];
    const float* bo    = (const float*)d_in[8];
    const float* gamma = (const float*)d_in[9];
    const float* beta  = (const float*)d_in[10];
    float* out = (float*)d_out;

    __half *xt, *wq, *wkv, *wo, *qt, *kv, *mt, *pp, *yp;
    float *bkv, *gsum, *gsq, *mean, *istd;
    cudaGetSymbolAddress((void**)&xt,  g_xt);
    cudaGetSymbolAddress((void**)&wq,  g_wq);
    cudaGetSymbolAddress((void**)&wkv, g_wkv);
    cudaGetSymbolAddress((void**)&wo,  g_wo);
    cudaGetSymbolAddress((void**)&qt,  g_qt);
    cudaGetSymbolAddress((void**)&kv,  g_kv);
    cudaGetSymbolAddress((void**)&mt,  g_mt);
    cudaGetSymbolAddress((void**)&pp,  g_p);
    cudaGetSymbolAddress((void**)&yp,  g_y);
    cudaGetSymbolAddress((void**)&bkv, g_bkv);
    cudaGetSymbolAddress((void**)&gsum, g_sum);
    cudaGetSymbolAddress((void**)&gsq,  g_sq);
    cudaGetSymbolAddress((void**)&mean, g_mean);
    cudaGetSymbolAddress((void**)&istd, g_istd);

    cudaFuncSetAttribute(wgemm<1, 3>, cudaFuncAttributeMaxDynamicSharedMemorySize, SMEM_B);
    cudaFuncSetAttribute(wgemm<2, 1>, cudaFuncAttributeMaxDynamicSharedMemorySize, SMEM_B);
    cudaFuncSetAttribute(wgemm<0, 1>, cudaFuncAttributeMaxDynamicSharedMemorySize, SMEM_B);
    cudaFuncSetAttribute(wgemm<1, 5>, cudaFuncAttributeMaxDynamicSharedMemorySize, SMEM_B);

    // second stream + fork/join events (created per call; replay runs only
    // the captured graph, so these host-side creations happen O(1) times)
    cudaStream_t s2;
    cudaStreamCreate(&s2);
    cudaEvent_t evF, evQ;
    cudaEventCreateWithFlags(&evF, cudaEventDisableTiming);
    cudaEventCreateWithFlags(&evQ, cudaEventDisableTiming);

    // conversions (main stream)
    xtrans<<<dim3(Tn / 32, Cn / 32, Bn), 256>>>(x, xt);
    const size_t nw4 = (size_t)Dn * Cn / 4;   // per weight tensor
    wconv4<<<dim3((unsigned)((nw4 + 255) / 256), 4), 256>>>(
        Wk, Wv, Wq, Wo, wkv, wkv + (size_t)Dn * Cn, wq, wo, nw4);
    packbias_zstats<<<4, 256>>>(bk, bv, bkv, gsum, gsq);

    const size_t sTC  = (size_t)Tn * Cn;
    const size_t sTD  = (size_t)Tn * Dn;
    const size_t s2DS = (size_t)2 * Dn * Sn;
    const size_t sDD  = (size_t)Dn * Dn;
    const size_t sCD  = (size_t)Cn * Dn;
    const size_t sCT  = (size_t)Cn * Tn;

    // fork: Q^T proj runs on s2, concurrent with KV -> Mt -> P on main
    cudaEventRecord(evF, 0);
    cudaStreamWaitEvent(s2, evF, 0);
    const dim3 gq(Dn / 128, Tn / 128, Bn);
    wgemm<2, 1><<<gq, 256, SMEM_B, s2>>>(xt, wq, bq, qt, nullptr, nullptr,
                                         Tn, Dn, Cn, 1.f, sTC, 0, sTD);
    cudaEventRecord(evQ, s2);

    // KV proj + fused pool: [Kp;Vp](2D,S) = pool2(Wkv x + bkv)
    const dim3 gkv(Tn / 128, 2 * Dn / 128, Bn);
    wgemm<1, 3><<<gkv, 256, SMEM_B>>>(wkv, xt, bkv, kv, nullptr, nullptr,
                                      2 * Dn, Tn, Cn, 1.f, 0, sTC, s2DS);

    // Mt(D,D) = Kp Vp^T  (= M^T)
    const dim3 gm(Dn / 128, Dn / 128, Bn);
    wgemm<0, 1><<<gm, 256, SMEM_B>>>(kv, kv + (size_t)Dn * Sn, nullptr, mt,
                                     nullptr, nullptr,
                                     Dn, Dn, Sn, 1.f, s2DS, s2DS, sDD);

    // P(C,D) = Wo M = Wo Mt^T
    const dim3 gp(Dn / 128, Cn / 128, Bn);
    wgemm<0, 1><<<gp, 256, SMEM_B>>>(wo, mt, nullptr, pp, nullptr, nullptr,
                                     Cn, Dn, Dn, 1.f, 0, sDD, sCD);

    // join: y needs both P (main) and Q^T (s2)
    cudaStreamWaitEvent(0, evQ, 0);

    // y(C,T) = (1/T) P Q + bo, with fused BN sum/sumsq atomics
    const dim3 gy(Tn / 128, Cn / 128, Bn);
    wgemm<1, 5><<<gy, 256, SMEM_B>>>(pp, qt, bo, yp, gsum, gsq,
                                     Cn, Tn, Dn, 1.f / (float)Tn, sCD, sTD, sCT);

    // finalize stats, then BN apply + residual
    bnfin<<<4, 256>>>(gsum, gsq, mean, istd);
    const size_t total4 = (size_t)Bn * Cn * Tn / 4;
    bn_apply<<<(unsigned)((total4 + 255) / 256), 256>>>(yp, x, mean, istd, gamma, beta, out);
}

// round 15
// speedup vs baseline: 1.1574x; 1.0278x over previous
#include <cuda_runtime.h>
#include <cuda_fp16.h>

#define Bn 16
#define Cn 1024
#define Tn 2048
#define Dn 512
#define Sn (Tn / 2)
#define EPSf 1e-5f

typedef unsigned int u32;

// ---------------- scratch (static device arrays) ----------------
__device__ __align__(16) __half g_xt [(size_t)Bn * Tn * Cn];        // x^T (B,T,C)
__device__ __align__(16) __half g_wq [Dn * Cn];
__device__ __align__(16) __half g_wkv[2 * Dn * Cn];                 // [Wk; Wv] stacked
__device__ __align__(16) __half g_wo [Cn * Dn];
__device__ __align__(16) __half g_qt [(size_t)Bn * Tn * Dn];        // Q^T (B,T,D)
__device__ __align__(16) __half g_kv [(size_t)Bn * 2 * Dn * Sn];    // [Kp; Vp] pooled (B,2D,S)
__device__ __align__(16) __half g_mt [(size_t)Bn * Dn * Dn];        // Mt = Kp Vp^T
__device__ __align__(16) __half g_p  [(size_t)Bn * Cn * Dn];        // P = Wo M
__device__ __align__(16) __half g_y  [(size_t)Bn * Cn * Tn];        // pre-BN y (fp16)
__device__ float g_bkv[2 * Dn];
__device__ float g_sum[Cn];
__device__ float g_sq [Cn];

// ---------------- PTX helpers ----------------
__device__ __forceinline__ u32 smem_u32(const void* p) {
    u32 a;
    asm("{ .reg .u64 t; cvta.to.shared.u64 t, %1; cvt.u32.u64 %0, t; }" : "=r"(a) : "l"(p));
    return a;
}

#define CPA16(dst, src) \
    asm volatile("cp.async.cg.shared.global [%0], [%1], 16;" :: "r"(dst), "l"(src) : "memory")
#define CP_COMMIT() asm volatile("cp.async.commit_group;" ::: "memory")

#define LDSM4(r, a) \
    asm volatile("ldmatrix.sync.aligned.m8n8.x4.shared.b16 {%0,%1,%2,%3}, [%4];" \
        : "=r"((r)[0]), "=r"((r)[1]), "=r"((r)[2]), "=r"((r)[3]) : "r"(a))

#define MMA_F16(d, a, b0, b1) \
    asm volatile("mma.sync.aligned.m16n8k16.row.col.f32.f16.f16.f32 " \
        "{%0,%1,%2,%3}, {%4,%5,%6,%7}, {%8,%9}, {%0,%1,%2,%3};" \
        : "+f"((d)[0]), "+f"((d)[1]), "+f"((d)[2]), "+f"((d)[3]) \
        : "r"((a)[0]), "r"((a)[1]), "r"((a)[2]), "r"((a)[3]), "r"(b0), "r"(b1))

__device__ __forceinline__ u32 pack_h2(float v0, float v1) {
    __half h0 = __float2half_rn(v0), h1 = __float2half_rn(v1);
    return (u32)__half_as_ushort(h0) | ((u32)__half_as_ushort(h1) << 16);
}

// ---------------- warp-MMA plain-fp16 GEMM (R12 mainloop, frozen) ----------
// C(M,N) = alpha * A(M,K) * Bt(N,K)^T + bias
// A, Bt row-major K-major fp16; fp32 accumulate. Requires K % 128 == 0.
// BIAS: 0 none, 1 per-row, 2 per-col.
// OMODE: 1 fp16; 3 pool2 along N -> fp16 (N halves);
//        5 fp16 + fused per-row (channel) sum/sumsq atomics for BatchNorm.
// CTA 128x128, 8 warps of 32x64, 256 thr, 2 CTA/SM; BK=64, 3-stage ring
// (prologue commits 2 groups; wait_group 1 at iter kt guarantees tile kt).
// Six mainloop variants (R8-R13) all pinned at ~0.26 MMA/cyc/SM = the sm_103
// mma.sync issue ceiling; all GEMMs measured at ~150 T MAC/s (ceiling).
#define TILE_B 18432           // 128 rows * 144 B
#define BUF_B  (2 * TILE_B)    // A, B
#define SMEM_B (3 * BUF_B)     // 3-stage = 110592 (2 CTAs = 216 KB)

template <int BIAS, int OMODE>
__global__ void __launch_bounds__(256, 2) wgemm(
    const __half* __restrict__ A, const __half* __restrict__ Bt,
    const float* __restrict__ bias,
    __half* __restrict__ Ch,
    float* __restrict__ gsum, float* __restrict__ gsq,
    int M, int N, int K, float alpha,
    size_t sA, size_t sB, size_t sC)
{
    extern __shared__ __align__(128) char smem[];
    const u32 sbase = smem_u32(smem);
    const int tid = threadIdx.x;
    const int lane = tid & 31;
    const int warp = tid >> 5;
    const int wr = warp >> 1;       // 0..3 -> 32-row block
    const int wc = warp & 1;        // 0..1 -> 64-col block

    A  += (size_t)blockIdx.z * sA;
    Bt += (size_t)blockIdx.z * sB;
    const size_t coff = (size_t)blockIdx.z * sC;

    const int brow = blockIdx.y * 128;
    const int bcol = blockIdx.x * 128;
    const int KT = K >> 6;          // number of BK=64 steps

    // ---- streaming load pointers (computed once) ----
    const int rA = tid >> 3;              // 0..31
    const int cA = (tid & 7) * 8;         // 0..56 halfs (16B chunks)
    const __half* pA = A  + (size_t)(brow + rA) * K + cA;
    const __half* pB = Bt + (size_t)(bcol + rA) * K + cA;
    const size_t rskip = (size_t)32 * K;  // next 32-row group
    const u32 dA = sbase + (u32)(rA * 144 + (tid & 7) * 16);
    const u32 dB = dA + TILE_B;

    auto load_at = [&](u32 bufoff, const __half* a, const __half* b) {
#pragma unroll
        for (int it = 0; it < 4; it++) {
            CPA16(dA + bufoff + (u32)it * (32 * 144), a + (size_t)it * rskip);
            CPA16(dB + bufoff + (u32)it * (32 * 144), b + (size_t)it * rskip);
        }
    };

    float acc[2][8][4];
#pragma unroll
    for (int i = 0; i < 2; i++)
#pragma unroll
        for (int j = 0; j < 8; j++)
#pragma unroll
            for (int q = 0; q < 4; q++) acc[i][j][q] = 0.f;

    // ---- 3-stage prologue: load k-tiles 0,1 (2 committed groups) ----
    load_at(0,     pA,      pB);      CP_COMMIT();
    load_at(BUF_B, pA + 64, pB + 64); CP_COMMIT();
    const __half* qA = pA + 128;
    const __half* qB = pB + 128;

    const u32 rowoff = (u32)(((lane >> 3) & 1) * 8 + (lane & 7));
    const u32 chsel  = (u32)(lane >> 4);
    const u32 aoff = (u32)(wr * 32 + rowoff) * 144 + chsel * 16;
    const u32 boff = TILE_B + (u32)(wc * 64 + rowoff) * 144 + chsel * 16;

    int buf = 0;
    for (int kt = 0; kt < KT; kt++) {
        asm volatile("cp.async.wait_group 1;" ::: "memory");
        __syncthreads();   // tile kt visible; next write buffer reusable

        if (kt + 2 < KT) {
            int nb = buf + 2; if (nb >= 3) nb -= 3;
            load_at((u32)nb * BUF_B, qA, qB);
            qA += 64; qB += 64;
        }
        CP_COMMIT();       // one group per iter (possibly empty at tail)

        const u32 at = sbase + (u32)buf * BUF_B;
        const u32 abase = at + aoff;
        const u32 bbase = at + boff;

        // ---- fragment-pipelined 4x k16 substeps ----
        u32 ar[2][4];        // A frags, single buffer
        u32 br[2][4][4];     // B frags, double buffer
#pragma unroll
        for (int j4 = 0; j4 < 4; j4++)
            LDSM4(br[0][j4], bbase + (u32)j4 * (16 * 144));
#pragma unroll
        for (int i = 0; i < 2; i++)
            LDSM4(ar[i], abase + (u32)i * (16 * 144));

#pragma unroll
        for (int ks = 0; ks < 4; ks++) {
            const int cur = ks & 1;
            const int nxt = cur ^ 1;
            const u32 nchoff = (u32)(ks + 1) * 32;
            if (ks < 3) {
#pragma unroll
                for (int j4 = 0; j4 < 4; j4++)
                    LDSM4(br[nxt][j4], bbase + (u32)j4 * (16 * 144) + nchoff);
            }
#pragma unroll
            for (int i = 0; i < 2; i++)
#pragma unroll
                for (int j = 0; j < 8; j++) {
                    const int j4 = j >> 1, h = j & 1;
                    MMA_F16(acc[i][j], ar[i], br[cur][j4][h], br[cur][j4][h + 2]);
                }
            if (ks < 3) {
#pragma unroll
                for (int i = 0; i < 2; i++)
                    LDSM4(ar[i], abase + (u32)i * (16 * 144) + nchoff);
            }
        }
        if (++buf == 3) buf = 0;
    }

    // ---------------- epilogue ----------------
    const int r0 = brow + wr * 32 + (lane >> 2);
    const int c0l = wc * 64 + (lane & 3) * 2;
#pragma unroll
    for (int i = 0; i < 2; i++) {
#pragma unroll
        for (int half = 0; half < 2; half++) {
            const int row = r0 + i * 16 + half * 8;
            const float badd = (BIAS == 1) ? bias[row] : 0.f;
            float st = 0.f, st2 = 0.f;
#pragma unroll
            for (int j = 0; j < 8; j++) {
                const int col = bcol + c0l + j * 8;
                float v0 = alpha * acc[i][j][half * 2 + 0] + badd;
                float v1 = alpha * acc[i][j][half * 2 + 1] + badd;
                if (BIAS == 2) { v0 += bias[col]; v1 += bias[col + 1]; }
                if (OMODE == 1 || OMODE == 5) {
                    *(u32*)(Ch + coff + (size_t)row * N + col) = pack_h2(v0, v1);
                    if (OMODE == 5) {
                        st  += v0 + v1;
                        st2 += v0 * v0 + v1 * v1;
                    }
                } else { // OMODE == 3: maxpool pairs of adjacent cols
                    Ch[coff + (size_t)row * (N >> 1) + (col >> 1)] =
                        __float2half_rn(fmaxf(v0, v1));
                }
            }
            if (OMODE == 5) {
                st  += __shfl_xor_sync(0xffffffffu, st,  1);
                st  += __shfl_xor_sync(0xffffffffu, st,  2);
                st2 += __shfl_xor_sync(0xffffffffu, st2, 1);
                st2 += __shfl_xor_sync(0xffffffffu, st2, 2);
                if ((lane & 3) == 0) {
                    atomicAdd(gsum + row, st);
                    atomicAdd(gsq  + row, st2);
                }
            }
        }
    }
}

// ---------------- x (B,C,T) fp32 -> x^T (B,T,C) fp16 ----------------
__global__ void xtrans(const float* __restrict__ x, __half* __restrict__ o)
{
    __shared__ float s[32][33];
    const int b = blockIdx.z;
    const int c0 = blockIdx.y * 32;
    const int t0 = blockIdx.x * 32;
    const int tid = threadIdx.x;
    for (int i = tid; i < 1024; i += 256) {
        const int r = i >> 5, cc = i & 31;
        s[r][cc] = x[((size_t)b * Cn + c0 + r) * Tn + t0 + cc];
    }
    __syncthreads();
    for (int i = tid; i < 512; i += 256) {
        const int r = i >> 4, cp = (i & 15) * 2;
        const size_t oo = ((size_t)b * Tn + t0 + r) * Cn + c0 + cp;
        *(u32*)(o + oo) = pack_h2(s[cp][r], s[cp + 1][r]);
    }
}

// ---------------- weight fp32->fp16 + bias pack + stat zero (one launch) ---
__global__ void wprep(const float* __restrict__ w0, const float* __restrict__ w1,
                      const float* __restrict__ w2, const float* __restrict__ w3,
                      __half* __restrict__ o0, __half* __restrict__ o1,
                      __half* __restrict__ o2, __half* __restrict__ o3,
                      const float* __restrict__ bk, const float* __restrict__ bv,
                      float* __restrict__ obias, float* __restrict__ gsum,
                      float* __restrict__ gsq, size_t n4)
{
    const size_t i = (size_t)blockIdx.x * blockDim.x + threadIdx.x;
    if (i < n4) {
        const float* srcs[4] = {w0, w1, w2, w3};
        __half* dsts[4] = {o0, o1, o2, o3};
        const float4 v = ((const float4*)srcs[blockIdx.y])[i];
        ((uint2*)dsts[blockIdx.y])[i] = make_uint2(pack_h2(v.x, v.y), pack_h2(v.z, v.w));
    }
    // fold bias pack + stat zeroing into plane y==0, first 4 blocks
    if (blockIdx.y == 0 && blockIdx.x < 4) {
        const int k = blockIdx.x * 256 + threadIdx.x;
        if (k < Dn) obias[k] = bk[k];
        else if (k < 2 * Dn) obias[k] = bv[k - Dn];
        if (k < Cn) { gsum[k] = 0.f; gsq[k] = 0.f; }
    }
}

// ---------------- BN finalize + apply + residual (fused, 1 row per block) --
__global__ void __launch_bounds__(256) bn_apply(
    const __half* __restrict__ y, const float* __restrict__ x,
    const float* __restrict__ gsum, const float* __restrict__ gsq,
    const float* __restrict__ gamma, const float* __restrict__ beta,
    float* __restrict__ out)
{
    const int bc = blockIdx.x;            // (b*Cn + c): one full T-row
    const int c = bc & (Cn - 1);
    __shared__ float sm, sg;
    if (threadIdx.x == 0) {
        const float n = (float)(Bn * Tn);
        const float m = gsum[c] / n;
        sm = m;
        sg = gamma[c] * rsqrtf(gsq[c] / n - m * m + EPSf);
    }
    __syncthreads();
    const float m = sm, g = sg, bt = beta[c];
    const size_t base = (size_t)bc * Tn + (size_t)threadIdx.x * 8;
    const uint4 u = *(const uint4*)(y + base);
    const u32 w[4] = {u.x, u.y, u.z, u.w};
    const float4 x0 = *(const float4*)(x + base);
    const float4 x1 = *(const float4*)(x + base + 4);
    float4 o0, o1;
    {
        const float2 f0 = __half22float2(*(const __half2*)&w[0]);
        const float2 f1 = __half22float2(*(const __half2*)&w[1]);
        o0.x = g * (f0.x - m) + bt + x0.x;
        o0.y = g * (f0.y - m) + bt + x0.y;
        o0.z = g * (f1.x - m) + bt + x0.z;
        o0.w = g * (f1.y - m) + bt + x0.w;
    }
    {
        const float2 f2 = __half22float2(*(const __half2*)&w[2]);
        const float2 f3 = __half22float2(*(const __half2*)&w[3]);
        o1.x = g * (f2.x - m) + bt + x1.x;
        o1.y = g * (f2.y - m) + bt + x1.y;
        o1.z = g * (f3.x - m) + bt + x1.z;
        o1.w = g * (f3.y - m) + bt + x1.w;
    }
    *(float4*)(out + base)     = o0;
    *(float4*)(out + base + 4) = o1;
}

extern "C" void kernel_launch(void* const* d_in, const int* in_sizes, int n_in,
                              void* d_out, int out_size)
{
    const float* x     = (const float*)d_in[0];
    const float* Wq    = (const float*)d_in[1];
    const float* bq    = (const float*)d_in[2];
    const float* Wk    = (const float*)d_in[3];
    const float* bk    = (const float*)d_in[4];
    const float* Wv    = (const float*)d_in[5];
    const float* bv    = (const float*)d_in[6];
    const float* Wo    = (const float*)d_in[7];
    const float* bo    = (const float*)d_in[8];
    const float* gamma = (const float*)d_in[9];
    const float* beta  = (const float*)d_in[10];
    float* out = (float*)d_out;

    __half *xt, *wq, *wkv, *wo, *qt, *kv, *mt, *pp, *yp;
    float *bkv, *gsum, *gsq;
    cudaGetSymbolAddress((void**)&xt,  g_xt);
    cudaGetSymbolAddress((void**)&wq,  g_wq);
    cudaGetSymbolAddress((void**)&wkv, g_wkv);
    cudaGetSymbolAddress((void**)&wo,  g_wo);
    cudaGetSymbolAddress((void**)&qt,  g_qt);
    cudaGetSymbolAddress((void**)&kv,  g_kv);
    cudaGetSymbolAddress((void**)&mt,  g_mt);
    cudaGetSymbolAddress((void**)&pp,  g_p);
    cudaGetSymbolAddress((void**)&yp,  g_y);
    cudaGetSymbolAddress((void**)&bkv, g_bkv);
    cudaGetSymbolAddress((void**)&gsum, g_sum);
    cudaGetSymbolAddress((void**)&gsq,  g_sq);

    cudaFuncSetAttribute(wgemm<1, 3>, cudaFuncAttributeMaxDynamicSharedMemorySize, SMEM_B);
    cudaFuncSetAttribute(wgemm<2, 1>, cudaFuncAttributeMaxDynamicSharedMemorySize, SMEM_B);
    cudaFuncSetAttribute(wgemm<0, 1>, cudaFuncAttributeMaxDynamicSharedMemorySize, SMEM_B);
    cudaFuncSetAttribute(wgemm<1, 5>, cudaFuncAttributeMaxDynamicSharedMemorySize, SMEM_B);

    // second stream + fork/join events (created per call; replay runs the
    // captured graph only, so these host creations happen O(1) times)
    cudaStream_t s2;
    cudaStreamCreate(&s2);
    cudaEvent_t evF, evQ, evW;
    cudaEventCreateWithFlags(&evF, cudaEventDisableTiming);
    cudaEventCreateWithFlags(&evQ, cudaEventDisableTiming);
    cudaEventCreateWithFlags(&evW, cudaEventDisableTiming);

    const size_t nw4 = (size_t)Dn * Cn / 4;   // per weight tensor

    // fork s2 off the capture stream first
    cudaEventRecord(evF, 0);
    cudaStreamWaitEvent(s2, evF, 0);

    // prep: weights+bias+stat-zero on s2, x transpose on main (independent)
    wprep<<<dim3((unsigned)((nw4 + 255) / 256), 4), 256, 0, s2>>>(
        Wk, Wv, Wq, Wo, wkv, wkv + (size_t)Dn * Cn, wq, wo,
        bk, bv, bkv, gsum, gsq, nw4);
    cudaEventRecord(evW, s2);
    xtrans<<<dim3(Tn / 32, Cn / 32, Bn), 256>>>(x, xt);
    cudaStreamWaitEvent(0, evW, 0);   // main waits for weights before GEMMs

    const size_t sTC  = (size_t)Tn * Cn;
    const size_t sTD  = (size_t)Tn * Dn;
    const size_t s2DS = (size_t)2 * Dn * Sn;
    const size_t sDD  = (size_t)Dn * Dn;
    const size_t sCD  = (size_t)Cn * Dn;
    const size_t sCT  = (size_t)Cn * Tn;

    // fork: Q^T proj on s2 (needs xt from main, evF2)
    cudaEvent_t evX;
    cudaEventCreateWithFlags(&evX, cudaEventDisableTiming);
    cudaEventRecord(evX, 0);
    cudaStreamWaitEvent(s2, evX, 0);
    const dim3 gq(Dn / 128, Tn / 128, Bn);
    wgemm<2, 1><<<gq, 256, SMEM_B, s2>>>(xt, wq, bq, qt, nullptr, nullptr,
                                         Tn, Dn, Cn, 1.f, sTC, 0, sTD);
    cudaEventRecord(evQ, s2);

    // KV proj + fused pool: [Kp;Vp](2D,S) = pool2(Wkv x + bkv)
    const dim3 gkv(Tn / 128, 2 * Dn / 128, Bn);
    wgemm<1, 3><<<gkv, 256, SMEM_B>>>(wkv, xt, bkv, kv, nullptr, nullptr,
                                      2 * Dn, Tn, Cn, 1.f, 0, sTC, s2DS);

    // Mt(D,D) = Kp Vp^T  (= M^T)
    const dim3 gm(Dn / 128, Dn / 128, Bn);
    wgemm<0, 1><<<gm, 256, SMEM_B>>>(kv, kv + (size_t)Dn * Sn, nullptr, mt,
                                     nullptr, nullptr,
                                     Dn, Dn, Sn, 1.f, s2DS, s2DS, sDD);

    // P(C,D) = Wo M = Wo Mt^T
    const dim3 gp(Dn / 128, Cn / 128, Bn);
    wgemm<0, 1><<<gp, 256, SMEM_B>>>(wo, mt, nullptr, pp, nullptr, nullptr,
                                     Cn, Dn, Dn, 1.f, 0, sDD, sCD);

    // join: y needs both P (main) and Q^T (s2)
    cudaStreamWaitEvent(0, evQ, 0);

    // y(C,T) = (1/T) P Q + bo, with fused BN sum/sumsq atomics
    const dim3 gy(Tn / 128, Cn / 128, Bn);
    wgemm<1, 5><<<gy, 256, SMEM_B>>>(pp, qt, bo, yp, gsum, gsq,
                                     Cn, Tn, Dn, 1.f / (float)Tn, sCD, sTD, sCT);

    // fused BN finalize + apply + residual: one block per (b,c) row
    bn_apply<<<Bn * Cn, 256>>>(yp, x, gsum, gsq, gamma, beta, out);
}